// round 15
// baseline (speedup 1.0000x reference)
#include <cuda_runtime.h>
#include <cuda_bf16.h>
#include <math.h>

#define T_STEPS 512
#define BATCH   64
#define IN_DIM  512
#define RNN_DIM 512

#define NCTA2   128   // 32 jblk x 4 bblk
#define NTHR2   256
#define GRP_SZ  32

typedef unsigned long long ull;
typedef unsigned int u32;

// scratch (no device allocs allowed)
__device__ float g_pre[(size_t)T_STEPS * BATCH * RNN_DIM];   // 64MB
__device__ float g_hT[2][RNN_DIM * BATCH];                    // [parity][r][b]
__device__ ull g_grp[4 * 16];                                 // group ctrs, 128B apart
// pre-split operands for the tensor GEMM
__device__ __nv_bfloat16 g_Xhi[(size_t)T_STEPS * BATCH * IN_DIM];  // 32MB
__device__ __nv_bfloat16 g_Xlo[(size_t)T_STEPS * BATCH * IN_DIM];  // 32MB
__device__ __nv_bfloat16 g_WThi[RNN_DIM * IN_DIM];                 // [n][k] 512KB
__device__ __nv_bfloat16 g_WTlo[RNN_DIM * IN_DIM];

extern __shared__ float smem_dyn[];

__device__ __forceinline__ void split_bf16(float x, __nv_bfloat16& h, __nv_bfloat16& l) {
    h = __float2bfloat16(x);
    l = __float2bfloat16(x - __bfloat162float(h));
}

// ---------------------------------------------------------------------------
// Phase 0: split X and W (rows 0..511) into bf16 hi/lo planes, once.
// Blocks [0, 4096): X — 4,194,304 float4 granules, 4 per thread:
//   gidx = (bid*256 + tid) + i*1048576   (max 4,194,303 — in bounds).
// Blocks [4096, 4160): W rows 0..511 transposed to [n][k].
// Block 0 also resets phase-2 barrier state.
// ---------------------------------------------------------------------------
__global__ __launch_bounds__(256) void split_kernel(
    const float* __restrict__ X,
    const float* __restrict__ W)
{
    const int tid = threadIdx.x;
    if (blockIdx.x == 0 && tid < 4)
        g_grp[tid * 16] = 0ULL;

    if (blockIdx.x < 4096) {
        size_t base = (size_t)blockIdx.x * 256 + tid;      // 0..1,048,575
        #pragma unroll
        for (int i = 0; i < 4; i++) {
            size_t gidx = base + (size_t)i * 1048576;      // < 4,194,304
            float4 v = *(const float4*)(X + gidx * 4);
            __nv_bfloat16 h0, h1, h2, h3, l0, l1, l2, l3;
            split_bf16(v.x, h0, l0); split_bf16(v.y, h1, l1);
            split_bf16(v.z, h2, l2); split_bf16(v.w, h3, l3);
            __nv_bfloat162* ph = (__nv_bfloat162*)(g_Xhi + gidx * 4);
            ph[0] = __halves2bfloat162(h0, h1);
            ph[1] = __halves2bfloat162(h2, h3);
            __nv_bfloat162* pl = (__nv_bfloat162*)(g_Xlo + gidx * 4);
            pl[0] = __halves2bfloat162(l0, l1);
            pl[1] = __halves2bfloat162(l2, l3);
        }
    } else {
        // W rows 0..511 -> transposed bf16 planes [n][k], 262,144 elements
        int e0 = (blockIdx.x - 4096) * 256 + tid;          // 0..16,383
        #pragma unroll
        for (int i = 0; i < 16; i++) {
            int e = e0 + i * 16384;                        // < 262,144
            int k = e >> 9, n = e & 511;
            float v = W[(size_t)k * RNN_DIM + n];
            __nv_bfloat16 h, l;
            split_bf16(v, h, l);
            g_WThi[(size_t)n * IN_DIM + k] = h;
            g_WTlo[(size_t)n * IN_DIM + k] = l;
        }
    }
}

// ---------------------------------------------------------------------------
// Phase 1: pre = X @ Wx + bias via bf16-split tensor-core GEMM.
// MMA core identical to R12; staging is pure coalesced uint4 copies.
// smem rows padded to 136 bf16 (cols 0..63 hi, 64..127 lo).
// ---------------------------------------------------------------------------
#define GBM 128
#define GBN 128
#define GKC 64
#define SROW 136
#define GSM_BYTES (2 * 128 * SROW * 2)   // A + B planes, 69632 B

__device__ __forceinline__ void mma_bf16(float c[4], const u32 a[4], const u32 b[2]) {
    asm volatile(
        "mma.sync.aligned.m16n8k16.row.col.f32.bf16.bf16.f32 "
        "{%0,%1,%2,%3}, {%4,%5,%6,%7}, {%8,%9}, {%0,%1,%2,%3};"
        : "+f"(c[0]), "+f"(c[1]), "+f"(c[2]), "+f"(c[3])
        : "r"(a[0]), "r"(a[1]), "r"(a[2]), "r"(a[3]), "r"(b[0]), "r"(b[1]));
}

__global__ __launch_bounds__(256) void gemm_pre_kernel(
    const float* __restrict__ bias)
{
    __nv_bfloat16* sA = (__nv_bfloat16*)smem_dyn;            // [128 m][SROW]
    __nv_bfloat16* sB = sA + 128 * SROW;                     // [128 n][SROW]

    const int tid  = threadIdx.x;
    const int lane = tid & 31;
    const int wid  = tid >> 5;
    const int bm   = blockIdx.x;
    const int bn   = blockIdx.y;

    const int warp_m = wid & 1;
    const int warp_n = wid >> 1;
    const int g   = lane >> 2;
    const int tig = lane & 3;

    float c[4][4][4];
    #pragma unroll
    for (int mi = 0; mi < 4; mi++)
        #pragma unroll
        for (int ni = 0; ni < 4; ni++)
            #pragma unroll
            for (int r = 0; r < 4; r++)
                c[mi][ni][r] = 0.0f;

    for (int kc = 0; kc < IN_DIM / GKC; kc++) {
        // ---- stage A: 2048 uint4 (hi+lo), 8 per thread, coalesced ----
        #pragma unroll
        for (int t = 0; t < 8; t++) {
            int e = tid + t * 256;          // [0,2048)
            int row = e >> 4;
            int sub = e & 15;
            int plane = sub >> 3;           // 0=hi,1=lo
            int q = sub & 7;                // 8 bf16 per uint4
            const __nv_bfloat16* src =
                (plane ? g_Xlo : g_Xhi) +
                ((size_t)(bm * GBM + row) * IN_DIM + kc * GKC + q * 8);
            *(uint4*)&sA[row * SROW + plane * 64 + q * 8] = *(const uint4*)src;
        }
        // ---- stage B: same pattern from transposed planes ----
        #pragma unroll
        for (int t = 0; t < 8; t++) {
            int e = tid + t * 256;
            int n = e >> 4;
            int sub = e & 15;
            int plane = sub >> 3;
            int q = sub & 7;
            const __nv_bfloat16* src =
                (plane ? g_WTlo : g_WThi) +
                ((size_t)(bn * GBN + n) * IN_DIM + kc * GKC + q * 8);
            *(uint4*)&sB[n * SROW + plane * 64 + q * 8] = *(const uint4*)src;
        }
        __syncthreads();

        // ---- 3 operand passes: (Ahi,Bhi), (Alo,Bhi), (Ahi,Blo) ----
        #pragma unroll
        for (int p = 0; p < 3; p++) {
            const int offA = (p == 1) ? 64 : 0;
            const int offB = (p == 2) ? 64 : 0;
            #pragma unroll
            for (int k16 = 0; k16 < 4; k16++) {
                const int ka = offA + k16 * 16 + 2 * tig;
                const int kb = offB + k16 * 16 + 2 * tig;
                u32 a[4][4];
                #pragma unroll
                for (int mi = 0; mi < 4; mi++) {
                    int r0 = warp_m * 64 + mi * 16 + g;
                    a[mi][0] = *(const u32*)&sA[(r0    ) * SROW + ka];
                    a[mi][1] = *(const u32*)&sA[(r0 + 8) * SROW + ka];
                    a[mi][2] = *(const u32*)&sA[(r0    ) * SROW + ka + 8];
                    a[mi][3] = *(const u32*)&sA[(r0 + 8) * SROW + ka + 8];
                }
                u32 b[4][2];
                #pragma unroll
                for (int ni = 0; ni < 4; ni++) {
                    int n0 = warp_n * 32 + ni * 8 + g;
                    b[ni][0] = *(const u32*)&sB[n0 * SROW + kb];
                    b[ni][1] = *(const u32*)&sB[n0 * SROW + kb + 8];
                }
                #pragma unroll
                for (int mi = 0; mi < 4; mi++)
                    #pragma unroll
                    for (int ni = 0; ni < 4; ni++)
                        mma_bf16(c[mi][ni], a[mi], b[ni]);
            }
        }
        __syncthreads();
    }

    // ---- epilogue: + bias, write g_pre ----
    #pragma unroll
    for (int mi = 0; mi < 4; mi++) {
        #pragma unroll
        for (int ni = 0; ni < 4; ni++) {
            int row = bm * GBM + warp_m * 64 + mi * 16 + g;
            int col = bn * GBN + warp_n * 32 + ni * 8 + 2 * tig;
            float b0 = bias[col], b1 = bias[col + 1];
            float2 v0 = make_float2(c[mi][ni][0] + b0, c[mi][ni][1] + b1);
            float2 v1 = make_float2(c[mi][ni][2] + b0, c[mi][ni][3] + b1);
            *(float2*)(g_pre + (size_t)row * RNN_DIM + col)       = v0;
            *(float2*)(g_pre + (size_t)(row + 8) * RNN_DIM + col) = v1;
        }
    }
}

// ---------------------------------------------------------------------------
// Phase 2: persistent RNN — R10 version byte-for-byte (best, sync-bound).
// ---------------------------------------------------------------------------
__device__ __forceinline__ void group_arrive(int grp)
{
    __syncthreads();
    if (threadIdx.x == 0) {
        __threadfence();
        atomicAdd(&g_grp[grp * 16], 1ULL);
    }
}
__device__ __forceinline__ void group_wait(int grp, ull step)
{
    if (threadIdx.x == 0) {
        volatile ull* ctr = (volatile ull*)&g_grp[grp * 16];
        ull need = (ull)GRP_SZ * step;
        while (*ctr < need) { }
        __threadfence();
    }
    __syncthreads();
}

__global__ __launch_bounds__(NTHR2) void rnn_seq_kernel(
    const float* __restrict__ W,
    const float* __restrict__ init_hidden,
    float* __restrict__ out)
{
    float* ws = smem_dyn;                 // [512][16] Wh slice, 32KB
    float* hs = smem_dyn + RNN_DIM * 16;  // [512][16] h slab, 32KB

    const int tid  = threadIdx.x;
    const int jblk = blockIdx.x & 31;
    const int bblk = blockIdx.x >> 5;
    const int j0 = jblk * 16;
    const int b0 = bblk * 16;

    #pragma unroll
    for (int i = 0; i < 8; i++) {
        int idx = tid + i * NTHR2;
        int r = idx >> 2, q = (idx & 3) * 4;
        *(float4*)&ws[r * 16 + q] =
            *(const float4*)(W + (size_t)(IN_DIM + r) * RNN_DIM + j0 + q);
    }

    {
        int b = tid >> 4, j = tid & 15;
        out[(size_t)(b0 + b) * RNN_DIM + j0 + j] = init_hidden[j0 + j];
    }
    if (jblk == 0) {
        int kbase = (tid >> 2) * 8;
        int q = (tid & 3) * 4;
        #pragma unroll
        for (int kk = 0; kk < 8; kk++) {
            int k = kbase + kk;
            float v = init_hidden[k];
            *(float4*)&g_hT[0][k * BATCH + b0 + q] = make_float4(v, v, v, v);
        }
    }
    group_arrive(bblk);

    const int kg = tid >> 4;
    const int tt = tid & 15;
    const int bq = (tt >> 2) * 4;
    const int jq = (tt & 3) * 4;
    const int fb = tid >> 4;
    const int fj = tid & 15;

    float pre = g_pre[((size_t)0 * BATCH + b0 + fb) * RNN_DIM + j0 + fj];
    group_wait(bblk, 1ULL);

    for (int t = 0; t < T_STEPS - 1; t++) {
        const float* hsrc = g_hT[t & 1];

        float4 r0[4];
        #pragma unroll
        for (int i = 0; i < 4; i++) {
            int idx = tid + i * NTHR2;
            int r = idx >> 2, q = (idx & 3) * 4;
            r0[i] = *(const float4*)(hsrc + r * BATCH + b0 + q);
        }
        #pragma unroll
        for (int i = 0; i < 4; i++) {
            int idx = tid + i * NTHR2;
            int r = idx >> 2, q = (idx & 3) * 4;
            *(float4*)&hs[r * 16 + q] = r0[i];
        }
        __syncthreads();

        float4 r1[4];
        #pragma unroll
        for (int i = 0; i < 4; i++) {
            int idx = tid + (i + 4) * NTHR2;
            int r = idx >> 2, q = (idx & 3) * 4;
            r1[i] = *(const float4*)(hsrc + r * BATCH + b0 + q);
        }

        float c[4][4];
        #pragma unroll
        for (int i = 0; i < 4; i++)
            #pragma unroll
            for (int j = 0; j < 4; j++)
                c[i][j] = 0.0f;

        #pragma unroll 4
        for (int kk = 0; kk < 16; kk++) {
            int k = kg + (kk << 4);
            float4 hv = *(float4*)&hs[k * 16 + bq];
            float4 wv = *(float4*)&ws[k * 16 + jq];
            c[0][0] += hv.x * wv.x; c[0][1] += hv.x * wv.y;
            c[0][2] += hv.x * wv.z; c[0][3] += hv.x * wv.w;
            c[1][0] += hv.y * wv.x; c[1][1] += hv.y * wv.y;
            c[1][2] += hv.y * wv.z; c[1][3] += hv.y * wv.w;
            c[2][0] += hv.z * wv.x; c[2][1] += hv.z * wv.y;
            c[2][2] += hv.z * wv.z; c[2][3] += hv.z * wv.w;
            c[3][0] += hv.w * wv.x; c[3][1] += hv.w * wv.y;
            c[3][2] += hv.w * wv.z; c[3][3] += hv.w * wv.w;
        }

        #pragma unroll
        for (int i = 0; i < 4; i++) {
            int idx = tid + (i + 4) * NTHR2;
            int r = idx >> 2, q = (idx & 3) * 4;
            *(float4*)&hs[r * 16 + q] = r1[i];
        }
        __syncthreads();

        #pragma unroll 4
        for (int kk = 16; kk < 32; kk++) {
            int k = kg + (kk << 4);
            float4 hv = *(float4*)&hs[k * 16 + bq];
            float4 wv = *(float4*)&ws[k * 16 + jq];
            c[0][0] += hv.x * wv.x; c[0][1] += hv.x * wv.y;
            c[0][2] += hv.x * wv.z; c[0][3] += hv.x * wv.w;
            c[1][0] += hv.y * wv.x; c[1][1] += hv.y * wv.y;
            c[1][2] += hv.y * wv.z; c[1][3] += hv.y * wv.w;
            c[2][0] += hv.z * wv.x; c[2][1] += hv.z * wv.y;
            c[2][2] += hv.z * wv.z; c[2][3] += hv.z * wv.w;
            c[3][0] += hv.w * wv.x; c[3][1] += hv.w * wv.y;
            c[3][2] += hv.w * wv.z; c[3][3] += hv.w * wv.w;
        }

        float* red = hs;
        #pragma unroll
        for (int i = 0; i < 4; i++)
            #pragma unroll
            for (int j = 0; j < 4; j++)
                red[kg * 256 + (bq + i) * 16 + (jq + j)] = c[i][j];
        __syncthreads();

        float s = 0.0f;
        #pragma unroll
        for (int gg = 0; gg < 16; gg++)
            s += red[gg * 256 + tid];
        float h = tanhf(s + pre);
        g_hT[(t + 1) & 1][(j0 + fj) * BATCH + b0 + fb] = h;

        if (t < T_STEPS - 2) {
            group_arrive(bblk);
            out[((size_t)(t + 1) * BATCH + b0 + fb) * RNN_DIM + j0 + fj] = h;
            pre = g_pre[((size_t)(t + 1) * BATCH + b0 + fb) * RNN_DIM + j0 + fj];
            group_wait(bblk, (ull)(t + 2));
        } else {
            out[((size_t)(t + 1) * BATCH + b0 + fb) * RNN_DIM + j0 + fj] = h;
        }
    }
}

// ---------------------------------------------------------------------------
extern "C" void kernel_launch(void* const* d_in, const int* in_sizes, int n_in,
                              void* d_out, int out_size)
{
    const float* X    = (const float*)d_in[0];  // [T, B, IN_DIM]
    const float* W    = (const float*)d_in[1];  // [IN_DIM + RNN_DIM, RNN_DIM]
    const float* bias = (const float*)d_in[2];  // [RNN_DIM]
    const float* h0   = (const float*)d_in[3];  // [RNN_DIM]
    float* out = (float*)d_out;                 // [T, B, RNN_DIM]

    cudaFuncSetAttribute(gemm_pre_kernel,
                         cudaFuncAttributeMaxDynamicSharedMemorySize, GSM_BYTES);
    cudaFuncSetAttribute(rnn_seq_kernel,
                         cudaFuncAttributeMaxDynamicSharedMemorySize, 65536);

    split_kernel<<<4160, 256>>>(X, W);

    dim3 g1((T_STEPS * BATCH) / GBM, RNN_DIM / GBN);  // (256, 4)
    gemm_pre_kernel<<<g1, 256, GSM_BYTES>>>(bias);

    rnn_seq_kernel<<<NCTA2, NTHR2, 65536>>>(W, h0, out);
}

// round 16
// speedup vs baseline: 1.1335x; 1.1335x over previous
#include <cuda_runtime.h>
#include <cuda_bf16.h>
#include <math.h>

#define T_STEPS 512
#define BATCH   64
#define IN_DIM  512
#define RNN_DIM 512

#define NCTA2   128   // 32 jblk x 4 bblk
#define NTHR2   256
#define GRP_SZ  32

typedef unsigned long long ull;
typedef unsigned int u32;

// scratch (no device allocs allowed)
__device__ float g_pre[(size_t)T_STEPS * BATCH * RNN_DIM];   // 64MB
__device__ float g_hT[2][RNN_DIM * BATCH];                    // [parity][r][b]
__device__ ull g_grp[4 * 16];                                 // group ctrs, 128B apart
// pre-split, pre-transposed W planes [n][k] (small, L2-resident)
__device__ __nv_bfloat16 g_WThi[RNN_DIM * IN_DIM];            // 512KB
__device__ __nv_bfloat16 g_WTlo[RNN_DIM * IN_DIM];            // 512KB

extern __shared__ float smem_dyn[];

__device__ __forceinline__ void split_bf16(float x, __nv_bfloat16& h, __nv_bfloat16& l) {
    h = __float2bfloat16(x);
    l = __float2bfloat16(x - __bfloat162float(h));
}

// ---------------------------------------------------------------------------
// Phase 0: split+transpose W rows 0..511 -> [n][k] bf16 hi/lo planes (once).
// 64 blocks x 256 threads x 16 elements = 262,144. Block 0 resets barriers.
// ---------------------------------------------------------------------------
__global__ __launch_bounds__(256) void wsplit_kernel(const float* __restrict__ W)
{
    const int tid = threadIdx.x;
    if (blockIdx.x == 0 && tid < 4)
        g_grp[tid * 16] = 0ULL;

    int e0 = blockIdx.x * 256 + tid;               // 0..16,383
    #pragma unroll
    for (int i = 0; i < 16; i++) {
        int e = e0 + i * 16384;                    // < 262,144
        int k = e >> 9, n = e & 511;
        float v = W[(size_t)k * RNN_DIM + n];
        __nv_bfloat16 h, l;
        split_bf16(v, h, l);
        g_WThi[(size_t)n * IN_DIM + k] = h;
        g_WTlo[(size_t)n * IN_DIM + k] = l;
    }
}

// ---------------------------------------------------------------------------
// Phase 1: pre = X @ Wx + bias via bf16-split tensor-core GEMM.
// X split in-kernel (read fp32 once, convert in regs — R12 pattern).
// W staged as pure coalesced uint4 copies from pre-split planes.
// MMA core and accumulation order identical to R12.
// ---------------------------------------------------------------------------
#define GBM 128
#define GBN 128
#define GKC 64
#define SROW 136
#define GSM_BYTES (2 * 128 * SROW * 2)   // A + B planes, 69632 B

__device__ __forceinline__ void mma_bf16(float c[4], const u32 a[4], const u32 b[2]) {
    asm volatile(
        "mma.sync.aligned.m16n8k16.row.col.f32.bf16.bf16.f32 "
        "{%0,%1,%2,%3}, {%4,%5,%6,%7}, {%8,%9}, {%0,%1,%2,%3};"
        : "+f"(c[0]), "+f"(c[1]), "+f"(c[2]), "+f"(c[3])
        : "r"(a[0]), "r"(a[1]), "r"(a[2]), "r"(a[3]), "r"(b[0]), "r"(b[1]));
}

__global__ __launch_bounds__(256) void gemm_pre_kernel(
    const float* __restrict__ X,
    const float* __restrict__ bias)
{
    __nv_bfloat16* sA = (__nv_bfloat16*)smem_dyn;            // [128 m][SROW]
    __nv_bfloat16* sB = sA + 128 * SROW;                     // [128 n][SROW]

    const int tid  = threadIdx.x;
    const int lane = tid & 31;
    const int wid  = tid >> 5;
    const int bm   = blockIdx.x;
    const int bn   = blockIdx.y;

    const int warp_m = wid & 1;
    const int warp_n = wid >> 1;
    const int g   = lane >> 2;
    const int tig = lane & 3;

    const float* Aptr = X + (size_t)bm * GBM * IN_DIM;

    float c[4][4][4];
    #pragma unroll
    for (int mi = 0; mi < 4; mi++)
        #pragma unroll
        for (int ni = 0; ni < 4; ni++)
            #pragma unroll
            for (int r = 0; r < 4; r++)
                c[mi][ni][r] = 0.0f;

    for (int kc = 0; kc < IN_DIM / GKC; kc++) {
        // ---- stage X chunk [128 m][64 k] as hi|lo (float4 reads, in-reg split) ----
        #pragma unroll
        for (int t = 0; t < 8; t++) {
            int e = tid + t * 256;            // 2048 float4 granules
            int row = e >> 4;
            int kq  = (e & 15) * 4;
            float4 v = *(const float4*)(Aptr + (size_t)row * IN_DIM + kc * GKC + kq);
            __nv_bfloat16 h0, h1, h2, h3, l0, l1, l2, l3;
            split_bf16(v.x, h0, l0); split_bf16(v.y, h1, l1);
            split_bf16(v.z, h2, l2); split_bf16(v.w, h3, l3);
            __nv_bfloat162* pH = (__nv_bfloat162*)&sA[row * SROW + kq];
            pH[0] = __halves2bfloat162(h0, h1);
            pH[1] = __halves2bfloat162(h2, h3);
            __nv_bfloat162* pL = (__nv_bfloat162*)&sA[row * SROW + 64 + kq];
            pL[0] = __halves2bfloat162(l0, l1);
            pL[1] = __halves2bfloat162(l2, l3);
        }
        // ---- stage W chunk: pure coalesced uint4 copies from pre-split planes ----
        #pragma unroll
        for (int t = 0; t < 8; t++) {
            int e = tid + t * 256;            // [0,2048)
            int n = e >> 4;
            int sub = e & 15;
            int plane = sub >> 3;             // 0=hi,1=lo
            int q = sub & 7;                  // 8 bf16 per uint4
            const __nv_bfloat16* src =
                (plane ? g_WTlo : g_WThi) +
                ((size_t)(bn * GBN + n) * IN_DIM + kc * GKC + q * 8);
            *(uint4*)&sB[n * SROW + plane * 64 + q * 8] = *(const uint4*)src;
        }
        __syncthreads();

        // ---- 3 operand passes: (Ahi,Bhi), (Alo,Bhi), (Ahi,Blo) ----
        #pragma unroll
        for (int p = 0; p < 3; p++) {
            const int offA = (p == 1) ? 64 : 0;
            const int offB = (p == 2) ? 64 : 0;
            #pragma unroll
            for (int k16 = 0; k16 < 4; k16++) {
                const int ka = offA + k16 * 16 + 2 * tig;
                const int kb = offB + k16 * 16 + 2 * tig;
                u32 a[4][4];
                #pragma unroll
                for (int mi = 0; mi < 4; mi++) {
                    int r0 = warp_m * 64 + mi * 16 + g;
                    a[mi][0] = *(const u32*)&sA[(r0    ) * SROW + ka];
                    a[mi][1] = *(const u32*)&sA[(r0 + 8) * SROW + ka];
                    a[mi][2] = *(const u32*)&sA[(r0    ) * SROW + ka + 8];
                    a[mi][3] = *(const u32*)&sA[(r0 + 8) * SROW + ka + 8];
                }
                u32 b[4][2];
                #pragma unroll
                for (int ni = 0; ni < 4; ni++) {
                    int n0 = warp_n * 32 + ni * 8 + g;
                    b[ni][0] = *(const u32*)&sB[n0 * SROW + kb];
                    b[ni][1] = *(const u32*)&sB[n0 * SROW + kb + 8];
                }
                #pragma unroll
                for (int mi = 0; mi < 4; mi++)
                    #pragma unroll
                    for (int ni = 0; ni < 4; ni++)
                        mma_bf16(c[mi][ni], a[mi], b[ni]);
            }
        }
        __syncthreads();
    }

    // ---- epilogue: + bias, write g_pre ----
    #pragma unroll
    for (int mi = 0; mi < 4; mi++) {
        #pragma unroll
        for (int ni = 0; ni < 4; ni++) {
            int row = bm * GBM + warp_m * 64 + mi * 16 + g;
            int col = bn * GBN + warp_n * 32 + ni * 8 + 2 * tig;
            float b0 = bias[col], b1 = bias[col + 1];
            float2 v0 = make_float2(c[mi][ni][0] + b0, c[mi][ni][1] + b1);
            float2 v1 = make_float2(c[mi][ni][2] + b0, c[mi][ni][3] + b1);
            *(float2*)(g_pre + (size_t)row * RNN_DIM + col)       = v0;
            *(float2*)(g_pre + (size_t)(row + 8) * RNN_DIM + col) = v1;
        }
    }
}

// ---------------------------------------------------------------------------
// Phase 2: persistent RNN — R10 version byte-for-byte (best, sync-bound).
// ---------------------------------------------------------------------------
__device__ __forceinline__ void group_arrive(int grp)
{
    __syncthreads();
    if (threadIdx.x == 0) {
        __threadfence();
        atomicAdd(&g_grp[grp * 16], 1ULL);
    }
}
__device__ __forceinline__ void group_wait(int grp, ull step)
{
    if (threadIdx.x == 0) {
        volatile ull* ctr = (volatile ull*)&g_grp[grp * 16];
        ull need = (ull)GRP_SZ * step;
        while (*ctr < need) { }
        __threadfence();
    }
    __syncthreads();
}

__global__ __launch_bounds__(NTHR2) void rnn_seq_kernel(
    const float* __restrict__ W,
    const float* __restrict__ init_hidden,
    float* __restrict__ out)
{
    float* ws = smem_dyn;                 // [512][16] Wh slice, 32KB
    float* hs = smem_dyn + RNN_DIM * 16;  // [512][16] h slab, 32KB

    const int tid  = threadIdx.x;
    const int jblk = blockIdx.x & 31;
    const int bblk = blockIdx.x >> 5;
    const int j0 = jblk * 16;
    const int b0 = bblk * 16;

    #pragma unroll
    for (int i = 0; i < 8; i++) {
        int idx = tid + i * NTHR2;
        int r = idx >> 2, q = (idx & 3) * 4;
        *(float4*)&ws[r * 16 + q] =
            *(const float4*)(W + (size_t)(IN_DIM + r) * RNN_DIM + j0 + q);
    }

    {
        int b = tid >> 4, j = tid & 15;
        out[(size_t)(b0 + b) * RNN_DIM + j0 + j] = init_hidden[j0 + j];
    }
    if (jblk == 0) {
        int kbase = (tid >> 2) * 8;
        int q = (tid & 3) * 4;
        #pragma unroll
        for (int kk = 0; kk < 8; kk++) {
            int k = kbase + kk;
            float v = init_hidden[k];
            *(float4*)&g_hT[0][k * BATCH + b0 + q] = make_float4(v, v, v, v);
        }
    }
    group_arrive(bblk);

    const int kg = tid >> 4;
    const int tt = tid & 15;
    const int bq = (tt >> 2) * 4;
    const int jq = (tt & 3) * 4;
    const int fb = tid >> 4;
    const int fj = tid & 15;

    float pre = g_pre[((size_t)0 * BATCH + b0 + fb) * RNN_DIM + j0 + fj];
    group_wait(bblk, 1ULL);

    for (int t = 0; t < T_STEPS - 1; t++) {
        const float* hsrc = g_hT[t & 1];

        float4 r0[4];
        #pragma unroll
        for (int i = 0; i < 4; i++) {
            int idx = tid + i * NTHR2;
            int r = idx >> 2, q = (idx & 3) * 4;
            r0[i] = *(const float4*)(hsrc + r * BATCH + b0 + q);
        }
        #pragma unroll
        for (int i = 0; i < 4; i++) {
            int idx = tid + i * NTHR2;
            int r = idx >> 2, q = (idx & 3) * 4;
            *(float4*)&hs[r * 16 + q] = r0[i];
        }
        __syncthreads();

        float4 r1[4];
        #pragma unroll
        for (int i = 0; i < 4; i++) {
            int idx = tid + (i + 4) * NTHR2;
            int r = idx >> 2, q = (idx & 3) * 4;
            r1[i] = *(const float4*)(hsrc + r * BATCH + b0 + q);
        }

        float c[4][4];
        #pragma unroll
        for (int i = 0; i < 4; i++)
            #pragma unroll
            for (int j = 0; j < 4; j++)
                c[i][j] = 0.0f;

        #pragma unroll 4
        for (int kk = 0; kk < 16; kk++) {
            int k = kg + (kk << 4);
            float4 hv = *(float4*)&hs[k * 16 + bq];
            float4 wv = *(float4*)&ws[k * 16 + jq];
            c[0][0] += hv.x * wv.x; c[0][1] += hv.x * wv.y;
            c[0][2] += hv.x * wv.z; c[0][3] += hv.x * wv.w;
            c[1][0] += hv.y * wv.x; c[1][1] += hv.y * wv.y;
            c[1][2] += hv.y * wv.z; c[1][3] += hv.y * wv.w;
            c[2][0] += hv.z * wv.x; c[2][1] += hv.z * wv.y;
            c[2][2] += hv.z * wv.z; c[2][3] += hv.z * wv.w;
            c[3][0] += hv.w * wv.x; c[3][1] += hv.w * wv.y;
            c[3][2] += hv.w * wv.z; c[3][3] += hv.w * wv.w;
        }

        #pragma unroll
        for (int i = 0; i < 4; i++) {
            int idx = tid + (i + 4) * NTHR2;
            int r = idx >> 2, q = (idx & 3) * 4;
            *(float4*)&hs[r * 16 + q] = r1[i];
        }
        __syncthreads();

        #pragma unroll 4
        for (int kk = 16; kk < 32; kk++) {
            int k = kg + (kk << 4);
            float4 hv = *(float4*)&hs[k * 16 + bq];
            float4 wv = *(float4*)&ws[k * 16 + jq];
            c[0][0] += hv.x * wv.x; c[0][1] += hv.x * wv.y;
            c[0][2] += hv.x * wv.z; c[0][3] += hv.x * wv.w;
            c[1][0] += hv.y * wv.x; c[1][1] += hv.y * wv.y;
            c[1][2] += hv.y * wv.z; c[1][3] += hv.y * wv.w;
            c[2][0] += hv.z * wv.x; c[2][1] += hv.z * wv.y;
            c[2][2] += hv.z * wv.z; c[2][3] += hv.z * wv.w;
            c[3][0] += hv.w * wv.x; c[3][1] += hv.w * wv.y;
            c[3][2] += hv.w * wv.z; c[3][3] += hv.w * wv.w;
        }

        float* red = hs;
        #pragma unroll
        for (int i = 0; i < 4; i++)
            #pragma unroll
            for (int j = 0; j < 4; j++)
                red[kg * 256 + (bq + i) * 16 + (jq + j)] = c[i][j];
        __syncthreads();

        float s = 0.0f;
        #pragma unroll
        for (int gg = 0; gg < 16; gg++)
            s += red[gg * 256 + tid];
        float h = tanhf(s + pre);
        g_hT[(t + 1) & 1][(j0 + fj) * BATCH + b0 + fb] = h;

        if (t < T_STEPS - 2) {
            group_arrive(bblk);
            out[((size_t)(t + 1) * BATCH + b0 + fb) * RNN_DIM + j0 + fj] = h;
            pre = g_pre[((size_t)(t + 1) * BATCH + b0 + fb) * RNN_DIM + j0 + fj];
            group_wait(bblk, (ull)(t + 2));
        } else {
            out[((size_t)(t + 1) * BATCH + b0 + fb) * RNN_DIM + j0 + fj] = h;
        }
    }
}

// ---------------------------------------------------------------------------
extern "C" void kernel_launch(void* const* d_in, const int* in_sizes, int n_in,
                              void* d_out, int out_size)
{
    const float* X    = (const float*)d_in[0];  // [T, B, IN_DIM]
    const float* W    = (const float*)d_in[1];  // [IN_DIM + RNN_DIM, RNN_DIM]
    const float* bias = (const float*)d_in[2];  // [RNN_DIM]
    const float* h0   = (const float*)d_in[3];  // [RNN_DIM]
    float* out = (float*)d_out;                 // [T, B, RNN_DIM]

    cudaFuncSetAttribute(gemm_pre_kernel,
                         cudaFuncAttributeMaxDynamicSharedMemorySize, GSM_BYTES);
    cudaFuncSetAttribute(rnn_seq_kernel,
                         cudaFuncAttributeMaxDynamicSharedMemorySize, 65536);

    wsplit_kernel<<<64, 256>>>(W);

    dim3 g1((T_STEPS * BATCH) / GBM, RNN_DIM / GBN);  // (256, 4)
    gemm_pre_kernel<<<g1, 256, GSM_BYTES>>>(X, bias);

    rnn_seq_kernel<<<NCTA2, NTHR2, 65536>>>(W, h0, out);
}

// round 17
// speedup vs baseline: 1.1491x; 1.0138x over previous
#include <cuda_runtime.h>
#include <cuda_bf16.h>
#include <math.h>

#define T_STEPS 512
#define BATCH   64
#define IN_DIM  512
#define RNN_DIM 512

#define NCTA2   128   // 32 jblk x 4 bblk
#define NTHR2   256
#define GRP_SZ  32

typedef unsigned long long ull;
typedef unsigned int u32;

// scratch (no device allocs allowed)
__device__ float g_pre[(size_t)T_STEPS * BATCH * RNN_DIM];   // 64MB
__device__ float g_hT[2][RNN_DIM * BATCH];                    // [parity][r][b]
__device__ ull g_grp[4 * 16];                                 // group ctrs, 128B apart
// pre-split, pre-transposed W planes [n][k] (small, L2-resident)
__device__ __nv_bfloat16 g_WThi[RNN_DIM * IN_DIM];            // 512KB
__device__ __nv_bfloat16 g_WTlo[RNN_DIM * IN_DIM];            // 512KB

extern __shared__ float smem_dyn[];

__device__ __forceinline__ void split_bf16(float x, __nv_bfloat16& h, __nv_bfloat16& l) {
    h = __float2bfloat16(x);
    l = __float2bfloat16(x - __bfloat162float(h));
}

// ---------------------------------------------------------------------------
// Phase 0: split+transpose W rows 0..511 -> [n][k] bf16 hi/lo planes (once).
// ---------------------------------------------------------------------------
__global__ __launch_bounds__(256) void wsplit_kernel(const float* __restrict__ W)
{
    const int tid = threadIdx.x;
    if (blockIdx.x == 0 && tid < 4)
        g_grp[tid * 16] = 0ULL;

    int e0 = blockIdx.x * 256 + tid;               // 0..16,383
    #pragma unroll
    for (int i = 0; i < 16; i++) {
        int e = e0 + i * 16384;                    // < 262,144
        int k = e >> 9, n = e & 511;
        float v = W[(size_t)k * RNN_DIM + n];
        __nv_bfloat16 h, l;
        split_bf16(v, h, l);
        g_WThi[(size_t)n * IN_DIM + k] = h;
        g_WTlo[(size_t)n * IN_DIM + k] = l;
    }
}

// ---------------------------------------------------------------------------
// Phase 1: pre = X @ Wx + bias via bf16-split tensor-core GEMM.
// Fragment loads via ldmatrix.x4, hoisted once per k16 and reused by the
// 3 split passes (Ahi*Bhi, Alo*Bhi, Ahi*Blo).
// ---------------------------------------------------------------------------
#define GBM 128
#define GBN 128
#define GKC 64
#define SROW 136
#define GSM_BYTES (2 * 128 * SROW * 2)   // A + B planes, 69632 B

__device__ __forceinline__ void mma_bf16(float c[4], const u32 a[4], const u32 b[2]) {
    asm volatile(
        "mma.sync.aligned.m16n8k16.row.col.f32.bf16.bf16.f32 "
        "{%0,%1,%2,%3}, {%4,%5,%6,%7}, {%8,%9}, {%0,%1,%2,%3};"
        : "+f"(c[0]), "+f"(c[1]), "+f"(c[2]), "+f"(c[3])
        : "r"(a[0]), "r"(a[1]), "r"(a[2]), "r"(a[3]), "r"(b[0]), "r"(b[1]));
}

__device__ __forceinline__ void ldsm4(u32 r[4], u32 addr) {
    asm volatile(
        "ldmatrix.sync.aligned.m8n8.x4.shared.b16 {%0,%1,%2,%3}, [%4];"
        : "=r"(r[0]), "=r"(r[1]), "=r"(r[2]), "=r"(r[3]) : "r"(addr));
}

__global__ __launch_bounds__(256) void gemm_pre_kernel(
    const float* __restrict__ X,
    const float* __restrict__ bias)
{
    __nv_bfloat16* sA = (__nv_bfloat16*)smem_dyn;            // [128 m][SROW]
    __nv_bfloat16* sB = sA + 128 * SROW;                     // [128 n][SROW]

    const int tid  = threadIdx.x;
    const int lane = tid & 31;
    const int wid  = tid >> 5;
    const int bm   = blockIdx.x;
    const int bn   = blockIdx.y;

    const int warp_m = wid & 1;
    const int warp_n = wid >> 1;
    const int g   = lane >> 2;
    const int tig = lane & 3;

    const float* Aptr = X + (size_t)bm * GBM * IN_DIM;

    // ldmatrix lane-address components (bytes)
    const u32 sA_base = (u32)__cvta_generic_to_shared(sA);
    const u32 sB_base = (u32)__cvta_generic_to_shared(sB);
    // A x4: matrices [m0-7|k0-7], [m8-15|k0-7], [m0-7|k8-15], [m8-15|k8-15]
    const u32 a_lane = (u32)((((lane & 7) + ((lane >> 3) & 1) * 8) * SROW
                              + (lane >> 4) * 8) * 2);
    // B x4: matrices [n0-7|k0-7], [n0-7|k8-15], [n8-15|k0-7], [n8-15|k8-15]
    const u32 b_lane = (u32)((((lane >> 4) * 8 + (lane & 7)) * SROW
                              + ((lane >> 3) & 1) * 8) * 2);
    const u32 aw = sA_base + (u32)(warp_m * 64 * SROW * 2) + a_lane;
    const u32 bw = sB_base + (u32)(warp_n * 32 * SROW * 2) + b_lane;

    float c[4][4][4];
    #pragma unroll
    for (int mi = 0; mi < 4; mi++)
        #pragma unroll
        for (int ni = 0; ni < 4; ni++)
            #pragma unroll
            for (int r = 0; r < 4; r++)
                c[mi][ni][r] = 0.0f;

    for (int kc = 0; kc < IN_DIM / GKC; kc++) {
        // ---- stage X chunk [128 m][64 k] as hi|lo (float4 reads, in-reg split) ----
        #pragma unroll
        for (int t = 0; t < 8; t++) {
            int e = tid + t * 256;
            int row = e >> 4;
            int kq  = (e & 15) * 4;
            float4 v = *(const float4*)(Aptr + (size_t)row * IN_DIM + kc * GKC + kq);
            __nv_bfloat16 h0, h1, h2, h3, l0, l1, l2, l3;
            split_bf16(v.x, h0, l0); split_bf16(v.y, h1, l1);
            split_bf16(v.z, h2, l2); split_bf16(v.w, h3, l3);
            __nv_bfloat162* pH = (__nv_bfloat162*)&sA[row * SROW + kq];
            pH[0] = __halves2bfloat162(h0, h1);
            pH[1] = __halves2bfloat162(h2, h3);
            __nv_bfloat162* pL = (__nv_bfloat162*)&sA[row * SROW + 64 + kq];
            pL[0] = __halves2bfloat162(l0, l1);
            pL[1] = __halves2bfloat162(l2, l3);
        }
        // ---- stage W chunk: pure coalesced uint4 copies from pre-split planes ----
        #pragma unroll
        for (int t = 0; t < 8; t++) {
            int e = tid + t * 256;
            int n = e >> 4;
            int sub = e & 15;
            int plane = sub >> 3;
            int q = sub & 7;
            const __nv_bfloat16* src =
                (plane ? g_WTlo : g_WThi) +
                ((size_t)(bn * GBN + n) * IN_DIM + kc * GKC + q * 8);
            *(uint4*)&sB[n * SROW + plane * 64 + q * 8] = *(const uint4*)src;
        }
        __syncthreads();

        // ---- mainloop: frag loads hoisted per k16, reused by 3 passes ----
        #pragma unroll
        for (int k16 = 0; k16 < 4; k16++) {
            const u32 ko = (u32)(k16 * 16 * 2);     // byte offset in k
            u32 ahi[4][4], alo[4][4];
            #pragma unroll
            for (int mi = 0; mi < 4; mi++) {
                u32 am = aw + (u32)(mi * 16 * SROW * 2) + ko;
                ldsm4(ahi[mi], am);
                ldsm4(alo[mi], am + 64 * 2);
            }
            u32 bhi[4][2], blo[4][2];
            #pragma unroll
            for (int np = 0; np < 2; np++) {        // ni pairs {0,1},{2,3}
                u32 bmadr = bw + (u32)(np * 16 * SROW * 2) + ko;
                u32 t4[4];
                ldsm4(t4, bmadr);
                bhi[2*np][0] = t4[0]; bhi[2*np][1] = t4[1];
                bhi[2*np+1][0] = t4[2]; bhi[2*np+1][1] = t4[3];
                ldsm4(t4, bmadr + 64 * 2);
                blo[2*np][0] = t4[0]; blo[2*np][1] = t4[1];
                blo[2*np+1][0] = t4[2]; blo[2*np+1][1] = t4[3];
            }
            // pass 0: Ahi x Bhi
            #pragma unroll
            for (int mi = 0; mi < 4; mi++)
                #pragma unroll
                for (int ni = 0; ni < 4; ni++)
                    mma_bf16(c[mi][ni], ahi[mi], bhi[ni]);
            // pass 1: Alo x Bhi
            #pragma unroll
            for (int mi = 0; mi < 4; mi++)
                #pragma unroll
                for (int ni = 0; ni < 4; ni++)
                    mma_bf16(c[mi][ni], alo[mi], bhi[ni]);
            // pass 2: Ahi x Blo
            #pragma unroll
            for (int mi = 0; mi < 4; mi++)
                #pragma unroll
                for (int ni = 0; ni < 4; ni++)
                    mma_bf16(c[mi][ni], ahi[mi], blo[ni]);
        }
        __syncthreads();
    }

    // ---- epilogue: + bias, write g_pre ----
    #pragma unroll
    for (int mi = 0; mi < 4; mi++) {
        #pragma unroll
        for (int ni = 0; ni < 4; ni++) {
            int row = bm * GBM + warp_m * 64 + mi * 16 + g;
            int col = bn * GBN + warp_n * 32 + ni * 8 + 2 * tig;
            float b0 = bias[col], b1 = bias[col + 1];
            float2 v0 = make_float2(c[mi][ni][0] + b0, c[mi][ni][1] + b1);
            float2 v1 = make_float2(c[mi][ni][2] + b0, c[mi][ni][3] + b1);
            *(float2*)(g_pre + (size_t)row * RNN_DIM + col)       = v0;
            *(float2*)(g_pre + (size_t)(row + 8) * RNN_DIM + col) = v1;
        }
    }
}

// ---------------------------------------------------------------------------
// Phase 2: persistent RNN — R10 version byte-for-byte (best, sync-bound).
// ---------------------------------------------------------------------------
__device__ __forceinline__ void group_arrive(int grp)
{
    __syncthreads();
    if (threadIdx.x == 0) {
        __threadfence();
        atomicAdd(&g_grp[grp * 16], 1ULL);
    }
}
__device__ __forceinline__ void group_wait(int grp, ull step)
{
    if (threadIdx.x == 0) {
        volatile ull* ctr = (volatile ull*)&g_grp[grp * 16];
        ull need = (ull)GRP_SZ * step;
        while (*ctr < need) { }
        __threadfence();
    }
    __syncthreads();
}

__global__ __launch_bounds__(NTHR2) void rnn_seq_kernel(
    const float* __restrict__ W,
    const float* __restrict__ init_hidden,
    float* __restrict__ out)
{
    float* ws = smem_dyn;                 // [512][16] Wh slice, 32KB
    float* hs = smem_dyn + RNN_DIM * 16;  // [512][16] h slab, 32KB

    const int tid  = threadIdx.x;
    const int jblk = blockIdx.x & 31;
    const int bblk = blockIdx.x >> 5;
    const int j0 = jblk * 16;
    const int b0 = bblk * 16;

    #pragma unroll
    for (int i = 0; i < 8; i++) {
        int idx = tid + i * NTHR2;
        int r = idx >> 2, q = (idx & 3) * 4;
        *(float4*)&ws[r * 16 + q] =
            *(const float4*)(W + (size_t)(IN_DIM + r) * RNN_DIM + j0 + q);
    }

    {
        int b = tid >> 4, j = tid & 15;
        out[(size_t)(b0 + b) * RNN_DIM + j0 + j] = init_hidden[j0 + j];
    }
    if (jblk == 0) {
        int kbase = (tid >> 2) * 8;
        int q = (tid & 3) * 4;
        #pragma unroll
        for (int kk = 0; kk < 8; kk++) {
            int k = kbase + kk;
            float v = init_hidden[k];
            *(float4*)&g_hT[0][k * BATCH + b0 + q] = make_float4(v, v, v, v);
        }
    }
    group_arrive(bblk);

    const int kg = tid >> 4;
    const int tt = tid & 15;
    const int bq = (tt >> 2) * 4;
    const int jq = (tt & 3) * 4;
    const int fb = tid >> 4;
    const int fj = tid & 15;

    float pre = g_pre[((size_t)0 * BATCH + b0 + fb) * RNN_DIM + j0 + fj];
    group_wait(bblk, 1ULL);

    for (int t = 0; t < T_STEPS - 1; t++) {
        const float* hsrc = g_hT[t & 1];

        float4 r0[4];
        #pragma unroll
        for (int i = 0; i < 4; i++) {
            int idx = tid + i * NTHR2;
            int r = idx >> 2, q = (idx & 3) * 4;
            r0[i] = *(const float4*)(hsrc + r * BATCH + b0 + q);
        }
        #pragma unroll
        for (int i = 0; i < 4; i++) {
            int idx = tid + i * NTHR2;
            int r = idx >> 2, q = (idx & 3) * 4;
            *(float4*)&hs[r * 16 + q] = r0[i];
        }
        __syncthreads();

        float4 r1[4];
        #pragma unroll
        for (int i = 0; i < 4; i++) {
            int idx = tid + (i + 4) * NTHR2;
            int r = idx >> 2, q = (idx & 3) * 4;
            r1[i] = *(const float4*)(hsrc + r * BATCH + b0 + q);
        }

        float c[4][4];
        #pragma unroll
        for (int i = 0; i < 4; i++)
            #pragma unroll
            for (int j = 0; j < 4; j++)
                c[i][j] = 0.0f;

        #pragma unroll 4
        for (int kk = 0; kk < 16; kk++) {
            int k = kg + (kk << 4);
            float4 hv = *(float4*)&hs[k * 16 + bq];
            float4 wv = *(float4*)&ws[k * 16 + jq];
            c[0][0] += hv.x * wv.x; c[0][1] += hv.x * wv.y;
            c[0][2] += hv.x * wv.z; c[0][3] += hv.x * wv.w;
            c[1][0] += hv.y * wv.x; c[1][1] += hv.y * wv.y;
            c[1][2] += hv.y * wv.z; c[1][3] += hv.y * wv.w;
            c[2][0] += hv.z * wv.x; c[2][1] += hv.z * wv.y;
            c[2][2] += hv.z * wv.z; c[2][3] += hv.z * wv.w;
            c[3][0] += hv.w * wv.x; c[3][1] += hv.w * wv.y;
            c[3][2] += hv.w * wv.z; c[3][3] += hv.w * wv.w;
        }

        #pragma unroll
        for (int i = 0; i < 4; i++) {
            int idx = tid + (i + 4) * NTHR2;
            int r = idx >> 2, q = (idx & 3) * 4;
            *(float4*)&hs[r * 16 + q] = r1[i];
        }
        __syncthreads();

        #pragma unroll 4
        for (int kk = 16; kk < 32; kk++) {
            int k = kg + (kk << 4);
            float4 hv = *(float4*)&hs[k * 16 + bq];
            float4 wv = *(float4*)&ws[k * 16 + jq];
            c[0][0] += hv.x * wv.x; c[0][1] += hv.x * wv.y;
            c[0][2] += hv.x * wv.z; c[0][3] += hv.x * wv.w;
            c[1][0] += hv.y * wv.x; c[1][1] += hv.y * wv.y;
            c[1][2] += hv.y * wv.z; c[1][3] += hv.y * wv.w;
            c[2][0] += hv.z * wv.x; c[2][1] += hv.z * wv.y;
            c[2][2] += hv.z * wv.z; c[2][3] += hv.z * wv.w;
            c[3][0] += hv.w * wv.x; c[3][1] += hv.w * wv.y;
            c[3][2] += hv.w * wv.z; c[3][3] += hv.w * wv.w;
        }

        float* red = hs;
        #pragma unroll
        for (int i = 0; i < 4; i++)
            #pragma unroll
            for (int j = 0; j < 4; j++)
                red[kg * 256 + (bq + i) * 16 + (jq + j)] = c[i][j];
        __syncthreads();

        float s = 0.0f;
        #pragma unroll
        for (int gg = 0; gg < 16; gg++)
            s += red[gg * 256 + tid];
        float h = tanhf(s + pre);
        g_hT[(t + 1) & 1][(j0 + fj) * BATCH + b0 + fb] = h;

        if (t < T_STEPS - 2) {
            group_arrive(bblk);
            out[((size_t)(t + 1) * BATCH + b0 + fb) * RNN_DIM + j0 + fj] = h;
            pre = g_pre[((size_t)(t + 1) * BATCH + b0 + fb) * RNN_DIM + j0 + fj];
            group_wait(bblk, (ull)(t + 2));
        } else {
            out[((size_t)(t + 1) * BATCH + b0 + fb) * RNN_DIM + j0 + fj] = h;
        }
    }
}

// ---------------------------------------------------------------------------
extern "C" void kernel_launch(void* const* d_in, const int* in_sizes, int n_in,
                              void* d_out, int out_size)
{
    const float* X    = (const float*)d_in[0];  // [T, B, IN_DIM]
    const float* W    = (const float*)d_in[1];  // [IN_DIM + RNN_DIM, RNN_DIM]
    const float* bias = (const float*)d_in[2];  // [RNN_DIM]
    const float* h0   = (const float*)d_in[3];  // [RNN_DIM]
    float* out = (float*)d_out;                 // [T, B, RNN_DIM]

    cudaFuncSetAttribute(gemm_pre_kernel,
                         cudaFuncAttributeMaxDynamicSharedMemorySize, GSM_BYTES);
    cudaFuncSetAttribute(rnn_seq_kernel,
                         cudaFuncAttributeMaxDynamicSharedMemorySize, 65536);

    wsplit_kernel<<<64, 256>>>(W);

    dim3 g1((T_STEPS * BATCH) / GBM, RNN_DIM / GBN);  // (256, 4)
    gemm_pre_kernel<<<g1, 256, GSM_BYTES>>>(X, bias);

    rnn_seq_kernel<<<NCTA2, NTHR2, 65536>>>(W, h0, out);
}